// round 1
// baseline (speedup 1.0000x reference)
#include <cuda_runtime.h>
#include <cuda_bf16.h>
#include <cstdint>

// ---------------------------------------------------------------------------
// GCN: out = relu(Agg(relu(Agg(x@W1)+b1)@W2)+b2) @ Wout + bout
// Agg(h)[i] = dinv[i]^2*h[i] + sum_{e: col[e]=i} dinv[row]*dinv[col]*h[row]
// ---------------------------------------------------------------------------

#define NN 100000
#define EE 1600000
#define DIM 128

// Scratch (zero-init .bss, no runtime allocation)
__device__ float g_bufA[(size_t)NN * DIM];
__device__ float g_bufB[(size_t)NN * DIM];
__device__ float g_bufC[(size_t)NN * DIM];
__device__ float g_deg[NN];
__device__ float g_dinv[NN];

// ---------------------------- degree / dinv --------------------------------
__global__ void k_deg_init(float* __restrict__ deg, int n) {
    int i = blockIdx.x * blockDim.x + threadIdx.x;
    if (i < n) deg[i] = 1.0f;  // self loop
}

__global__ void k_deg_count(const int* __restrict__ col, float* __restrict__ deg, int e) {
    int i = blockIdx.x * blockDim.x + threadIdx.x;
    if (i < e) atomicAdd(&deg[col[i]], 1.0f);
}

__global__ void k_dinv(const float* __restrict__ deg, float* __restrict__ dinv, int n) {
    int i = blockIdx.x * blockDim.x + threadIdx.x;
    if (i < n) dinv[i] = rsqrtf(deg[i]);
}

// ---------------------------- fp32 GEMM (N=K=128) ---------------------------
// H = X @ W  [M,128]x[128,128]; also Hs = dinv^2 * H (self-loop term, fused).
// BM=64, BN=128, BK=32, 256 threads, 4x8 microtile per thread.
__global__ __launch_bounds__(256) void k_gemm128(
    const float* __restrict__ X, const float* __restrict__ W,
    float* __restrict__ H, float* __restrict__ Hs,
    const float* __restrict__ dinv, int M)
{
    __shared__ float xs[32][68];   // transposed x tile [k][row], pad 68 -> 16B-aligned rows
    __shared__ float ws[32][128];  // W tile [k][n]

    const int tid = threadIdx.x;
    const int tx = tid & 15;       // N direction (16)
    const int ty = tid >> 4;       // M direction (16)
    const int row0 = blockIdx.x * 64;

    float acc[4][8];
#pragma unroll
    for (int i = 0; i < 4; i++)
#pragma unroll
        for (int j = 0; j < 8; j++) acc[i][j] = 0.f;

    for (int k0 = 0; k0 < 128; k0 += 32) {
        // load X tile: 64 rows x 32 k (2 float4 per thread)
        {
            int r  = tid >> 3;  // 0..31
            int c4 = tid & 7;   // k-chunk
#pragma unroll
            for (int h = 0; h < 2; h++) {
                int rr = r + h * 32;
                int grow = row0 + rr;
                float4 v = make_float4(0.f, 0.f, 0.f, 0.f);
                if (grow < M)
                    v = *(const float4*)(X + (size_t)grow * DIM + k0 + c4 * 4);
                xs[c4 * 4 + 0][rr] = v.x;
                xs[c4 * 4 + 1][rr] = v.y;
                xs[c4 * 4 + 2][rr] = v.z;
                xs[c4 * 4 + 3][rr] = v.w;
            }
        }
        // load W tile: 32 k x 128 n (4 float4 per thread)
        {
            int kr = tid >> 5;  // 0..7
            int c  = tid & 31;  // float4 col
#pragma unroll
            for (int h = 0; h < 4; h++) {
                int kk = kr + h * 8;
                *(float4*)&ws[kk][c * 4] =
                    *(const float4*)(W + (size_t)(k0 + kk) * DIM + c * 4);
            }
        }
        __syncthreads();

#pragma unroll
        for (int k = 0; k < 32; k++) {
            float4 av = *(const float4*)&xs[k][ty * 4];
            float4 b0 = *(const float4*)&ws[k][tx * 8];
            float4 b1 = *(const float4*)&ws[k][tx * 8 + 4];
            float a[4] = {av.x, av.y, av.z, av.w};
            float b[8] = {b0.x, b0.y, b0.z, b0.w, b1.x, b1.y, b1.z, b1.w};
#pragma unroll
            for (int i = 0; i < 4; i++)
#pragma unroll
                for (int j = 0; j < 8; j++) acc[i][j] += a[i] * b[j];
        }
        __syncthreads();
    }

#pragma unroll
    for (int i = 0; i < 4; i++) {
        int row = row0 + ty * 4 + i;
        if (row >= M) break;
        float4 v0 = make_float4(acc[i][0], acc[i][1], acc[i][2], acc[i][3]);
        float4 v1 = make_float4(acc[i][4], acc[i][5], acc[i][6], acc[i][7]);
        float* hp = H + (size_t)row * DIM + tx * 8;
        *(float4*)hp       = v0;
        *(float4*)(hp + 4) = v1;
        if (Hs) {
            float d  = dinv[row];
            float dd = d * d;
            float* sp = Hs + (size_t)row * DIM + tx * 8;
            *(float4*)sp       = make_float4(dd * v0.x, dd * v0.y, dd * v0.z, dd * v0.w);
            *(float4*)(sp + 4) = make_float4(dd * v1.x, dd * v1.y, dd * v1.z, dd * v1.w);
        }
    }
}

// ---------------------------- edge scatter ----------------------------------
// One warp per edge. Agg[col] += dinv[row]*dinv[col] * H[row]  (float4 red)
__device__ __forceinline__ void atomic_add4(float* p, float4 v) {
#if __CUDA_ARCH__ >= 900
    atomicAdd(reinterpret_cast<float4*>(p), v);
#else
    atomicAdd(p + 0, v.x); atomicAdd(p + 1, v.y);
    atomicAdd(p + 2, v.z); atomicAdd(p + 3, v.w);
#endif
}

__global__ __launch_bounds__(256) void k_edge_scatter(
    const int* __restrict__ rows, const int* __restrict__ cols,
    const float* __restrict__ dinv,
    const float* __restrict__ H, float* __restrict__ Agg, int E)
{
    int w = (int)((blockIdx.x * (unsigned)blockDim.x + threadIdx.x) >> 5);
    int lane = threadIdx.x & 31;
    if (w >= E) return;
    int r = rows[w];
    int c = cols[w];
    float nrm = dinv[r] * dinv[c];
    float4 v = *(const float4*)(H + (size_t)r * DIM + lane * 4);
    atomic_add4(Agg + (size_t)c * DIM + lane * 4,
                make_float4(nrm * v.x, nrm * v.y, nrm * v.z, nrm * v.w));
}

// ---------------------------- bias + relu -----------------------------------
__global__ void k_bias_relu(float* __restrict__ B, const float* __restrict__ bias, int n4) {
    int i = blockIdx.x * blockDim.x + threadIdx.x;
    if (i >= n4) return;
    float4 v = ((float4*)B)[i];
    float4 bb = ((const float4*)bias)[i & 31];  // 128/4 = 32 float4s per row
    v.x = fmaxf(v.x + bb.x, 0.f);
    v.y = fmaxf(v.y + bb.y, 0.f);
    v.z = fmaxf(v.z + bb.z, 0.f);
    v.w = fmaxf(v.w + bb.w, 0.f);
    ((float4*)B)[i] = v;
}

// ---------------------------- output GEMM (128 -> 40) -----------------------
// 8 warps/block, one row per warp. Wout (128x40) staged in SMEM.
__global__ __launch_bounds__(256) void k_out_gemm(
    const float* __restrict__ X, const float* __restrict__ Wout,
    const float* __restrict__ bout, float* __restrict__ out, int M)
{
    __shared__ float ws[DIM * 40];
    __shared__ float bs[40];
    __shared__ float xr[8][DIM];

    int tid = threadIdx.x;
    for (int i = tid; i < DIM * 40; i += 256) ws[i] = Wout[i];
    if (tid < 40) bs[tid] = bout[tid];

    int w = tid >> 5, lane = tid & 31;
    int row = blockIdx.x * 8 + w;
    if (row < M)
        *(float4*)&xr[w][lane * 4] = *(const float4*)(X + (size_t)row * DIM + lane * 4);
    __syncthreads();
    if (row >= M) return;

    float acc0 = 0.f, acc1 = 0.f;
    int c1 = lane + 32;
#pragma unroll 8
    for (int k = 0; k < DIM; k++) {
        float xv = xr[w][k];
        acc0 += xv * ws[k * 40 + lane];
        if (c1 < 40) acc1 += xv * ws[k * 40 + c1];
    }
    out[(size_t)row * 40 + lane] = acc0 + bs[lane];
    if (c1 < 40) out[(size_t)row * 40 + c1] = acc1 + bs[c1];
}

// ---------------------------- launcher ---------------------------------------
extern "C" void kernel_launch(void* const* d_in, const int* in_sizes, int n_in,
                              void* d_out, int out_size)
{
    const float* x    = (const float*)d_in[0];
    const int*   ei   = (const int*)d_in[1];
    const float* W1   = (const float*)d_in[2];
    const float* b1   = (const float*)d_in[3];
    const float* W2   = (const float*)d_in[4];
    const float* b2   = (const float*)d_in[5];
    const float* Wout = (const float*)d_in[6];
    const float* bout = (const float*)d_in[7];

    const int N = in_sizes[0] / DIM;
    const int E = in_sizes[1] / 2;
    const int* row = ei;
    const int* col = ei + E;

    void *pa, *pb, *pc, *pdeg, *pdinv;
    cudaGetSymbolAddress(&pa, g_bufA);
    cudaGetSymbolAddress(&pb, g_bufB);
    cudaGetSymbolAddress(&pc, g_bufC);
    cudaGetSymbolAddress(&pdeg, g_deg);
    cudaGetSymbolAddress(&pdinv, g_dinv);
    float* A = (float*)pa;
    float* B = (float*)pb;
    float* C = (float*)pc;
    float* deg = (float*)pdeg;
    float* dinv = (float*)pdinv;

    // --- degrees / normalization ---
    k_deg_init<<<(N + 255) / 256, 256>>>(deg, N);
    k_deg_count<<<(E + 255) / 256, 256>>>(col, deg, E);
    k_dinv<<<(N + 255) / 256, 256>>>(deg, dinv, N);

    const int gemm_blocks = (N + 63) / 64;
    const int scat_blocks = (E + 7) / 8;   // 8 warps per block
    const int n4 = N * (DIM / 4);

    // --- layer 1 ---
    k_gemm128<<<gemm_blocks, 256>>>(x, W1, A, B, dinv, N);        // B = dinv^2 * (x@W1)
    k_edge_scatter<<<scat_blocks, 256>>>(row, col, dinv, A, B, E);
    k_bias_relu<<<(n4 + 255) / 256, 256>>>(B, b1, n4);

    // --- layer 2 ---
    k_gemm128<<<gemm_blocks, 256>>>(B, W2, A, C, dinv, N);        // C = dinv^2 * (B@W2)
    k_edge_scatter<<<scat_blocks, 256>>>(row, col, dinv, A, C, E);
    k_bias_relu<<<(n4 + 255) / 256, 256>>>(C, b2, n4);

    // --- output projection ---
    k_out_gemm<<<(N + 7) / 8, 256>>>(C, Wout, bout, (float*)d_out, N);
}

// round 3
// speedup vs baseline: 1.6684x; 1.6684x over previous
#include <cuda_runtime.h>
#include <cuda_bf16.h>
#include <cstdint>

// ---------------------------------------------------------------------------
// GCN: out = relu(Agg(relu(Agg(x@W1)+b1)@W2)+b2) @ Wout + bout
// Agg(h)[i] = dinv[i]^2*h[i] + sum_{e: col[e]=i} dinv[row]*dinv[col]*h[row]
// Strategy: build CSR (by col) once per launch, then gather-based aggregation
// with fused self-loop + bias + relu. GEMM = fp32 128x128 tile, 8x8 microtile.
// ---------------------------------------------------------------------------

#define NN 100000
#define EE 1600000
#define DIM 128
#define SCAN_B 1024

// Scratch (.bss, no runtime allocation)
__device__ float g_bufA[(size_t)NN * DIM];
__device__ float g_bufB[(size_t)NN * DIM];
__device__ int   g_cnt[NN];
__device__ float g_dinv[NN];
__device__ int   g_part[NN];
__device__ int   g_bsum[128];
__device__ int   g_rowptr[NN + 1];
__device__ int   g_cursor[NN];
__device__ int   g_edst[EE];
__device__ float g_ew[EE];

// ---------------------------- CSR build -------------------------------------
__global__ void k_count(const int* __restrict__ col, int* __restrict__ cnt, int e) {
    int i = blockIdx.x * blockDim.x + threadIdx.x;
    if (i < e) atomicAdd(&cnt[col[i]], 1);
}

__global__ void k_scan1(const int* __restrict__ cnt, int* __restrict__ part,
                        int* __restrict__ bsum, int n) {
    __shared__ int sh[SCAN_B];
    int t = threadIdx.x;
    int g = blockIdx.x * SCAN_B + t;
    int v = (g < n) ? cnt[g] : 0;
    sh[t] = v;
    __syncthreads();
    for (int off = 1; off < SCAN_B; off <<= 1) {
        int x = (t >= off) ? sh[t - off] : 0;
        __syncthreads();
        sh[t] += x;
        __syncthreads();
    }
    if (g < n) part[g] = sh[t] - v;              // exclusive
    if (t == SCAN_B - 1) bsum[blockIdx.x] = sh[t];
}

__global__ void k_scan2(int* bsum, int nb) {     // single block of 128
    __shared__ int sh[128];
    int t = threadIdx.x;
    int v = (t < nb) ? bsum[t] : 0;
    sh[t] = v;
    __syncthreads();
    for (int off = 1; off < 128; off <<= 1) {
        int x = (t >= off) ? sh[t - off] : 0;
        __syncthreads();
        sh[t] += x;
        __syncthreads();
    }
    if (t < nb) bsum[t] = sh[t] - v;             // exclusive
}

__global__ void k_scan3(const int* __restrict__ part, const int* __restrict__ bsum,
                        int* __restrict__ rowptr, int* __restrict__ cursor, int n, int e) {
    int g = blockIdx.x * blockDim.x + threadIdx.x;
    if (g < n) {
        rowptr[g] = part[g] + bsum[g / SCAN_B];
        cursor[g] = 0;
    }
    if (g == 0) rowptr[n] = e;
}

__global__ void k_dinv(const int* __restrict__ cnt, float* __restrict__ dinv, int n) {
    int i = blockIdx.x * blockDim.x + threadIdx.x;
    if (i < n) dinv[i] = rsqrtf((float)(cnt[i] + 1));
}

__global__ void k_bucket(const int* __restrict__ row, const int* __restrict__ col,
                         const float* __restrict__ dinv, const int* __restrict__ rowptr,
                         int* __restrict__ cursor, int* __restrict__ edst,
                         float* __restrict__ ew, int E) {
    int e = blockIdx.x * blockDim.x + threadIdx.x;
    if (e >= E) return;
    int c = col[e];
    int r = row[e];
    int p = rowptr[c] + atomicAdd(&cursor[c], 1);
    edst[p] = r;
    ew[p] = dinv[r] * dinv[c];
}

// ---------------------------- fp32 GEMM (N=K=128) ---------------------------
// 128x128 tile, 256 threads, 8x8 microtile, BK=32.
__global__ __launch_bounds__(256, 2) void k_gemm128(
    const float* __restrict__ X, const float* __restrict__ W,
    float* __restrict__ H, int M)
{
    __shared__ float xs[32][132];   // transposed [k][row]
    __shared__ float ws[32][132];   // [k][n]

    const int tid = threadIdx.x;
    const int tx = tid & 15;        // N dir
    const int ty = tid >> 4;        // M dir
    const int row0 = blockIdx.x * 128;

    float acc[8][8];
#pragma unroll
    for (int i = 0; i < 8; i++)
#pragma unroll
        for (int j = 0; j < 8; j++) acc[i][j] = 0.f;

    for (int k0 = 0; k0 < 128; k0 += 32) {
        // X tile: 128 rows x 32 k, stored transposed
        {
            int r  = tid >> 3;   // 0..31
            int c4 = tid & 7;    // k-chunk
#pragma unroll
            for (int h = 0; h < 4; h++) {
                int rr = r + h * 32;
                int grow = row0 + rr;
                float4 v = make_float4(0.f, 0.f, 0.f, 0.f);
                if (grow < M)
                    v = *(const float4*)(X + (size_t)grow * DIM + k0 + c4 * 4);
                xs[c4 * 4 + 0][rr] = v.x;
                xs[c4 * 4 + 1][rr] = v.y;
                xs[c4 * 4 + 2][rr] = v.z;
                xs[c4 * 4 + 3][rr] = v.w;
            }
        }
        // W tile: 32 k x 128 n
        {
            int kr = tid >> 5;   // 0..7
            int c  = tid & 31;
#pragma unroll
            for (int h = 0; h < 4; h++) {
                int kk = kr + h * 8;
                *(float4*)&ws[kk][c * 4] =
                    *(const float4*)(W + (size_t)(k0 + kk) * DIM + c * 4);
            }
        }
        __syncthreads();

#pragma unroll
        for (int k = 0; k < 32; k++) {
            float a[8], b[8];
            *(float4*)&a[0] = *(const float4*)&xs[k][ty * 8];
            *(float4*)&a[4] = *(const float4*)&xs[k][ty * 8 + 4];
            *(float4*)&b[0] = *(const float4*)&ws[k][tx * 8];
            *(float4*)&b[4] = *(const float4*)&ws[k][tx * 8 + 4];
#pragma unroll
            for (int i = 0; i < 8; i++)
#pragma unroll
                for (int j = 0; j < 8; j++) acc[i][j] += a[i] * b[j];
        }
        __syncthreads();
    }

#pragma unroll
    for (int i = 0; i < 8; i++) {
        int row = row0 + ty * 8 + i;
        if (row < M) {
            float* hp = H + (size_t)row * DIM + tx * 8;
            *(float4*)hp       = *(float4*)&acc[i][0];
            *(float4*)(hp + 4) = *(float4*)&acc[i][4];
        }
    }
}

// ---------------------------- gather aggregation ----------------------------
// One warp per node: out[i] = relu( dinv[i]^2*H[i] + sum_e ew[e]*H[edst[e]] + bias )
__global__ __launch_bounds__(512) void k_agg(
    const int* __restrict__ rowptr, const int* __restrict__ edst,
    const float* __restrict__ ew, const float* __restrict__ dinv,
    const float* __restrict__ H, const float* __restrict__ bias,
    float* __restrict__ out, int N)
{
    int w = (int)((blockIdx.x * (unsigned)blockDim.x + threadIdx.x) >> 5);
    int lane = threadIdx.x & 31;
    if (w >= N) return;

    int beg = rowptr[w];
    int end = rowptr[w + 1];
    float d = dinv[w];
    float dd = d * d;

    float4 self = *(const float4*)(H + (size_t)w * DIM + lane * 4);
    float4 acc = make_float4(dd * self.x, dd * self.y, dd * self.z, dd * self.w);

#pragma unroll 4
    for (int e = beg; e < end; e++) {
        int r = __ldg(&edst[e]);
        float wgt = __ldg(&ew[e]);
        float4 v = *(const float4*)(H + (size_t)r * DIM + lane * 4);
        acc.x += wgt * v.x;
        acc.y += wgt * v.y;
        acc.z += wgt * v.z;
        acc.w += wgt * v.w;
    }

    float4 bb = *(const float4*)(bias + lane * 4);
    acc.x = fmaxf(acc.x + bb.x, 0.f);
    acc.y = fmaxf(acc.y + bb.y, 0.f);
    acc.z = fmaxf(acc.z + bb.z, 0.f);
    acc.w = fmaxf(acc.w + bb.w, 0.f);
    *(float4*)(out + (size_t)w * DIM + lane * 4) = acc;
}

// ---------------------------- output GEMM (128 -> 40) -----------------------
__global__ __launch_bounds__(256) void k_out_gemm(
    const float* __restrict__ X, const float* __restrict__ Wout,
    const float* __restrict__ bout, float* __restrict__ out, int M)
{
    __shared__ float ws[DIM * 40];
    __shared__ float bs[40];
    __shared__ float xr[8][DIM];

    int tid = threadIdx.x;
    for (int i = tid; i < DIM * 40; i += 256) ws[i] = Wout[i];
    if (tid < 40) bs[tid] = bout[tid];

    int w = tid >> 5, lane = tid & 31;
    int row = blockIdx.x * 8 + w;
    if (row < M)
        *(float4*)&xr[w][lane * 4] = *(const float4*)(X + (size_t)row * DIM + lane * 4);
    __syncthreads();
    if (row >= M) return;

    float acc0 = 0.f, acc1 = 0.f;
    int c1 = lane + 32;
#pragma unroll 8
    for (int k = 0; k < DIM; k++) {
        float xv = xr[w][k];
        acc0 += xv * ws[k * 40 + lane];
        if (c1 < 40) acc1 += xv * ws[k * 40 + c1];
    }
    out[(size_t)row * 40 + lane] = acc0 + bs[lane];
    if (c1 < 40) out[(size_t)row * 40 + c1] = acc1 + bs[c1];
}

// ---------------------------- launcher ---------------------------------------
extern "C" void kernel_launch(void* const* d_in, const int* in_sizes, int n_in,
                              void* d_out, int out_size)
{
    const float* x    = (const float*)d_in[0];
    const int*   ei   = (const int*)d_in[1];
    const float* W1   = (const float*)d_in[2];
    const float* b1   = (const float*)d_in[3];
    const float* W2   = (const float*)d_in[4];
    const float* b2   = (const float*)d_in[5];
    const float* Wout = (const float*)d_in[6];
    const float* bout = (const float*)d_in[7];

    const int N = in_sizes[0] / DIM;
    const int E = in_sizes[1] / 2;
    const int* row = ei;
    const int* col = ei + E;

    void *pa, *pb, *pcnt, *pdinv, *ppart, *pbsum, *prp, *pcur, *pedst, *pew;
    cudaGetSymbolAddress(&pa, g_bufA);
    cudaGetSymbolAddress(&pb, g_bufB);
    cudaGetSymbolAddress(&pcnt, g_cnt);
    cudaGetSymbolAddress(&pdinv, g_dinv);
    cudaGetSymbolAddress(&ppart, g_part);
    cudaGetSymbolAddress(&pbsum, g_bsum);
    cudaGetSymbolAddress(&prp, g_rowptr);
    cudaGetSymbolAddress(&pcur, g_cursor);
    cudaGetSymbolAddress(&pedst, g_edst);
    cudaGetSymbolAddress(&pew, g_ew);

    float* A      = (float*)pa;
    float* B      = (float*)pb;
    int*   cnt    = (int*)pcnt;
    float* dinv   = (float*)pdinv;
    int*   part   = (int*)ppart;
    int*   bsum   = (int*)pbsum;
    int*   rowptr = (int*)prp;
    int*   cursor = (int*)pcur;
    int*   edst   = (int*)pedst;
    float* ew     = (float*)pew;

    const int nb = (N + SCAN_B - 1) / SCAN_B;

    // --- CSR build + normalization ---
    cudaMemsetAsync(cnt, 0, (size_t)N * sizeof(int));
    k_count<<<(E + 255) / 256, 256>>>(col, cnt, E);
    k_scan1<<<nb, SCAN_B>>>(cnt, part, bsum, N);
    k_scan2<<<1, 128>>>(bsum, nb);
    k_scan3<<<(N + 255) / 256, 256>>>(part, bsum, rowptr, cursor, N, E);
    k_dinv<<<(N + 255) / 256, 256>>>(cnt, dinv, N);
    k_bucket<<<(E + 255) / 256, 256>>>(row, col, dinv, rowptr, cursor, edst, ew, E);

    const int gemm_blocks = (N + 127) / 128;
    const int agg_blocks  = (N + 15) / 16;   // 16 warps per block, warp per node

    // --- layer 1 ---
    k_gemm128<<<gemm_blocks, 256>>>(x, W1, A, N);
    k_agg<<<agg_blocks, 512>>>(rowptr, edst, ew, dinv, A, b1, B, N);

    // --- layer 2 ---
    k_gemm128<<<gemm_blocks, 256>>>(B, W2, A, N);
    k_agg<<<agg_blocks, 512>>>(rowptr, edst, ew, dinv, A, b2, B, N);

    // --- output projection ---
    k_out_gemm<<<(N + 7) / 8, 256>>>(B, Wout, bout, (float*)d_out, N);
}